// round 4
// baseline (speedup 1.0000x reference)
#include <cuda_runtime.h>

#define NVOX   262144
#define NU     65536
#define C_IN   128
#define C_HID  64
#define K_OUT  20
#define TILE   128
#define NTILES (NVOX / TILE)
#define HS2    66            // hs row stride (floats), [v][j] layout
#define THREADS 512

typedef unsigned long long u64;

// ---- f32x2 packed-FMA helpers (sm_103a FFMA2) ----
__device__ __forceinline__ u64 bcast2(float a) {
    u64 r; asm("mov.b64 %0, {%1, %1};" : "=l"(r) : "f"(a)); return r;
}
__device__ __forceinline__ u64 pack2(float a, float b) {
    u64 r; asm("mov.b64 %0, {%1, %2};" : "=l"(r) : "f"(a), "f"(b)); return r;
}
__device__ __forceinline__ void fma2(u64& d, u64 a, u64 b) {
    asm("fma.rn.f32x2 %0, %1, %2, %0;" : "+l"(d) : "l"(a), "l"(b));
}
__device__ __forceinline__ u64 add2(u64 a, u64 b) {
    u64 r; asm("add.rn.f32x2 %0, %1, %2;" : "=l"(r) : "l"(a), "l"(b)); return r;
}
__device__ __forceinline__ float2 unpk(u64 v) {
    float2 r; asm("mov.b64 {%0, %1}, %2;" : "=f"(r.x), "=f"(r.y) : "l"(v)); return r;
}

// Scratch: rank[v] = position in unmasked_idx, or -1 if masked.
__device__ int g_rank[NVOX];

__global__ void rank_kernel(const int* __restrict__ ui, const int* __restrict__ mi) {
    int t = blockIdx.x * blockDim.x + threadIdx.x;
    if (t < NU)        g_rank[ui[t]]      = t;
    else if (t < NVOX) g_rank[mi[t - NU]] = -1;
}

struct __align__(16) Smem {
    float fs[C_IN * TILE];        // [c][v]  feats -> vox (prior merged into masked cols)
    float hs[TILE * HS2];         // [v][j]  hidden (then d after GEMM3)
    float w1s [C_IN * C_HID];     // [c][j]  (j-pairs natural u64)
    float w2s [C_HID * C_IN];     // [j][c]  (c-pairs natural u64)
    float sdbs[C_IN * C_HID];     // [c][j]
    u64   sscd[C_HID * K_OUT];    // dup'd (w,w) pairs
    u64   auxd[C_IN * K_OUT];     // dup'd (w,w) pairs
    float b1s[C_HID], lngs[C_HID], lnbs[C_HID], sdbbs[C_HID];
    float b2s[C_IN];
    float sscbs[K_OUT];
    float auxbs[K_OUT];
    float mus[TILE], rss[TILE];
    int   ranks[TILE];
};

__global__ void __launch_bounds__(THREADS, 1)
fused_kernel(const float* __restrict__ x3d,
             const float* __restrict__ w1,    const float* __restrict__ b1,
             const float* __restrict__ ln_g,  const float* __restrict__ ln_b,
             const float* __restrict__ w2,    const float* __restrict__ b2,
             const float* __restrict__ sdb_w, const float* __restrict__ sdb_b,
             const float* __restrict__ ssc_w, const float* __restrict__ ssc_b,
             const float* __restrict__ aux_w, const float* __restrict__ aux_b,
             float* __restrict__ out)
{
    extern __shared__ char smem_raw[];
    Smem* s = reinterpret_cast<Smem*>(smem_raw);
    const int t = threadIdx.x;

    // ---- one-time weight residency ----
    for (int i = t; i < C_IN * C_HID;  i += THREADS) s->w1s[i]  = w1[i];
    for (int i = t; i < C_HID * C_IN;  i += THREADS) s->w2s[i]  = w2[i];
    for (int i = t; i < C_IN * C_HID;  i += THREADS) s->sdbs[i] = sdb_w[i];
    for (int i = t; i < C_HID * K_OUT; i += THREADS) s->sscd[i] = bcast2(ssc_w[i]);
    for (int i = t; i < C_IN * K_OUT;  i += THREADS) s->auxd[i] = bcast2(aux_w[i]);
    if (t < C_HID) { s->b1s[t] = b1[t]; s->lngs[t] = ln_g[t]; s->lnbs[t] = ln_b[t]; s->sdbbs[t] = sdb_b[t]; }
    if (t < C_IN)  { s->b2s[t] = b2[t]; }
    if (t < K_OUT) { s->sscbs[t] = ssc_b[t]; s->auxbs[t] = aux_b[t]; }

    float* outsem = out + (size_t)K_OUT * NVOX;

    // GEMM1/3 layout: 2 v, 8 j per thread
    const int vg1 = t >> 3;            // 0..63, v0 = vg1*2
    const int jg1 = t & 7;             // 0..7,  j0 = jg1*8
    // GEMM2 layout: 2 v (split), 16 c per thread
    const int vg2 = t & 63;            // v0 = vg2, v1 = vg2+64
    const int cg2 = t >> 6;            // c0 = cg2*16
    // heads layout
    const int wrp  = t >> 5;
    const int lane = t & 31;

    for (int tile = blockIdx.x; tile < NTILES; tile += gridDim.x) {
        const int vbase = tile * TILE;
        __syncthreads();                       // previous tile fully consumed

        // ---- load feats tile [128 c][128 v], coalesced float4 ----
        #pragma unroll
        for (int it = 0; it < 8; ++it) {
            int i  = t + it * THREADS;         // 0..4095 float4s
            int c  = i >> 5;
            int vq = i & 31;
            *reinterpret_cast<float4*>(&s->fs[c * TILE + vq * 4]) =
                *reinterpret_cast<const float4*>(&x3d[(size_t)c * NVOX + vbase + vq * 4]);
        }
        if (t < TILE) s->ranks[t] = g_rank[vbase + t];
        __syncthreads();

        // ---- GEMM1: h = feats @ w1 + b1 ; acc over (v, j-pair) ----
        {
            u64 a0[4] = {}, a1[4] = {};
            const float* fp0 = &s->fs[vg1 * 2];
            const float* wp0 = &s->w1s[jg1 * 8];
            #pragma unroll 2
            for (int c = 0; c < C_IN; ++c) {
                u64 fp = *reinterpret_cast<const u64*>(fp0 + c * TILE);
                float2 f = unpk(fp);
                u64 d0 = bcast2(f.x), d1 = bcast2(f.y);
                ulonglong2 wa = *reinterpret_cast<const ulonglong2*>(wp0 + c * C_HID);
                ulonglong2 wb = *reinterpret_cast<const ulonglong2*>(wp0 + c * C_HID + 4);
                fma2(a0[0], d0, wa.x); fma2(a1[0], d1, wa.x);
                fma2(a0[1], d0, wa.y); fma2(a1[1], d1, wa.y);
                fma2(a0[2], d0, wb.x); fma2(a1[2], d1, wb.x);
                fma2(a0[3], d0, wb.y); fma2(a1[3], d1, wb.y);
            }
            const int v0 = vg1 * 2, j0 = jg1 * 8;
            #pragma unroll
            for (int jp = 0; jp < 4; ++jp) {
                u64 bb = *reinterpret_cast<const u64*>(&s->b1s[j0 + jp * 2]);
                *reinterpret_cast<u64*>(&s->hs[v0 * HS2 + j0 + jp * 2])       = add2(a0[jp], bb);
                *reinterpret_cast<u64*>(&s->hs[(v0 + 1) * HS2 + j0 + jp * 2]) = add2(a1[jp], bb);
            }
        }
        __syncthreads();

        // ---- LayerNorm stats: one thread per voxel over contiguous row ----
        if (t < TILE) {
            const float* hr = &s->hs[t * HS2];
            float sum = 0.f, ssum = 0.f;
            #pragma unroll 8
            for (int j = 0; j < C_HID; ++j) {
                float x = hr[j];
                sum += x; ssum += x * x;
            }
            float mu  = sum * (1.f / 64.f);
            float var = ssum * (1.f / 64.f) - mu * mu;
            s->mus[t] = mu;
            s->rss[t] = rsqrtf(var + 1e-5f);
        }
        __syncthreads();
        // ---- normalize + LeakyReLU ----
        #pragma unroll
        for (int it = 0; it < 16; ++it) {
            int i = t + it * THREADS;          // 0..8191
            int v = i >> 6, j = i & 63;
            float x = s->hs[v * HS2 + j];
            x = (x - s->mus[v]) * s->rss[v] * s->lngs[j] + s->lnbs[j];
            s->hs[v * HS2 + j] = x > 0.f ? x : 0.01f * x;
        }
        __syncthreads();

        // ---- GEMM2: prior = h @ w2 + b2 ; acc over (v, c-pair); merge masked into fs ----
        {
            const int v0 = vg2, v1 = vg2 + 64, c0 = cg2 * 16;
            const bool m0 = s->ranks[v0] < 0, m1 = s->ranks[v1] < 0;
            u64 acc0[8] = {}, acc1[8] = {};
            const float* hp0 = &s->hs[v0 * HS2];
            const float* hp1 = &s->hs[v1 * HS2];
            const float* wp  = &s->w2s[c0];
            #pragma unroll 2
            for (int j = 0; j < C_HID; ++j) {
                u64 d0 = bcast2(hp0[j]);
                u64 d1 = bcast2(hp1[j]);
                ulonglong2 wa = *reinterpret_cast<const ulonglong2*>(wp + j * C_IN);
                ulonglong2 wb = *reinterpret_cast<const ulonglong2*>(wp + j * C_IN + 4);
                ulonglong2 wc = *reinterpret_cast<const ulonglong2*>(wp + j * C_IN + 8);
                ulonglong2 wd = *reinterpret_cast<const ulonglong2*>(wp + j * C_IN + 12);
                fma2(acc0[0], d0, wa.x); fma2(acc1[0], d1, wa.x);
                fma2(acc0[1], d0, wa.y); fma2(acc1[1], d1, wa.y);
                fma2(acc0[2], d0, wb.x); fma2(acc1[2], d1, wb.x);
                fma2(acc0[3], d0, wb.y); fma2(acc1[3], d1, wb.y);
                fma2(acc0[4], d0, wc.x); fma2(acc1[4], d1, wc.x);
                fma2(acc0[5], d0, wc.y); fma2(acc1[5], d1, wc.y);
                fma2(acc0[6], d0, wd.x); fma2(acc1[6], d1, wd.x);
                fma2(acc0[7], d0, wd.y); fma2(acc1[7], d1, wd.y);
            }
            #pragma unroll
            for (int cp = 0; cp < 8; ++cp) {
                int c = c0 + cp * 2;
                float bx = s->b2s[c], by = s->b2s[c + 1];
                if (m0) {
                    float2 p = unpk(acc0[cp]);
                    s->fs[c * TILE + v0]       = p.x + bx;
                    s->fs[(c + 1) * TILE + v0] = p.y + by;
                }
                if (m1) {
                    float2 p = unpk(acc1[cp]);
                    s->fs[c * TILE + v1]       = p.x + bx;
                    s->fs[(c + 1) * TILE + v1] = p.y + by;
                }
            }
        }
        __syncthreads();

        // ---- GEMM3: d = leaky(vox @ sdb_w + sdb_b) ; acc over (v, j-pair) ----
        {
            u64 a0[4] = {}, a1[4] = {};
            const float* fp0 = &s->fs[vg1 * 2];
            const float* wp0 = &s->sdbs[jg1 * 8];
            #pragma unroll 2
            for (int c = 0; c < C_IN; ++c) {
                u64 fp = *reinterpret_cast<const u64*>(fp0 + c * TILE);
                float2 f = unpk(fp);
                u64 d0 = bcast2(f.x), d1 = bcast2(f.y);
                ulonglong2 wa = *reinterpret_cast<const ulonglong2*>(wp0 + c * C_HID);
                ulonglong2 wb = *reinterpret_cast<const ulonglong2*>(wp0 + c * C_HID + 4);
                fma2(a0[0], d0, wa.x); fma2(a1[0], d1, wa.x);
                fma2(a0[1], d0, wa.y); fma2(a1[1], d1, wa.y);
                fma2(a0[2], d0, wb.x); fma2(a1[2], d1, wb.x);
                fma2(a0[3], d0, wb.y); fma2(a1[3], d1, wb.y);
            }
            const int v0 = vg1 * 2, j0 = jg1 * 8;
            #pragma unroll
            for (int jp = 0; jp < 4; ++jp) {
                float bx = s->sdbbs[j0 + jp * 2], by = s->sdbbs[j0 + jp * 2 + 1];
                float2 p0 = unpk(a0[jp]), p1 = unpk(a1[jp]);
                float x0 = p0.x + bx; x0 = x0 > 0.f ? x0 : 0.01f * x0;
                float y0 = p0.y + by; y0 = y0 > 0.f ? y0 : 0.01f * y0;
                float x1 = p1.x + bx; x1 = x1 > 0.f ? x1 : 0.01f * x1;
                float y1 = p1.y + by; y1 = y1 > 0.f ? y1 : 0.01f * y1;
                *reinterpret_cast<u64*>(&s->hs[v0 * HS2 + j0 + jp * 2])       = pack2(x0, y0);
                *reinterpret_cast<u64*>(&s->hs[(v0 + 1) * HS2 + j0 + jp * 2]) = pack2(x1, y1);
            }
        }
        __syncthreads();

        // ---- GEMM4 (warps 0-5) + AUX (warps 6-15) concurrently ----
        if (wrp < 6) {
            // ssc head: d @ ssc_w + b -> out[k*NVOX + v]; warp handles k-quads
            for (int kq = wrp; kq < 10; kq += 6) {
                const int k0 = kq * 2;
                u64 accA0 = 0, accA1 = 0, accB0 = 0, accB1 = 0;
                const float* hp = &s->hs[lane * HS2];
                const u64* wd = &s->sscd[k0];
                #pragma unroll 4
                for (int j = 0; j < C_HID; ++j) {
                    float dA = hp[j];
                    float dB = hp[32 * HS2 + j];
                    float dC = hp[64 * HS2 + j];
                    float dD = hp[96 * HS2 + j];
                    u64 p0 = pack2(dA, dB);
                    u64 p1 = pack2(dC, dD);
                    u64 w0 = wd[j * K_OUT];
                    u64 w1v = wd[j * K_OUT + 1];
                    fma2(accA0, p0, w0); fma2(accA1, p0, w1v);
                    fma2(accB0, p1, w0); fma2(accB1, p1, w1v);
                }
                float b0 = s->sscbs[k0], b1v = s->sscbs[k0 + 1];
                float2 qA0 = unpk(accA0), qA1 = unpk(accA1);
                float2 qB0 = unpk(accB0), qB1 = unpk(accB1);
                float* o0 = &out[(size_t)k0 * NVOX + vbase];
                float* o1 = &out[(size_t)(k0 + 1) * NVOX + vbase];
                o0[lane]      = qA0.x + b0;  o1[lane]      = qA1.x + b1v;
                o0[lane + 32] = qA0.y + b0;  o1[lane + 32] = qA1.y + b1v;
                o0[lane + 64] = qB0.x + b0;  o1[lane + 64] = qB1.x + b1v;
                o0[lane + 96] = qB0.y + b0;  o1[lane + 96] = qB1.y + b1v;
            }
        } else {
            // AUX head on unmasked columns of fs (original feats)
            const int kq = wrp - 6;            // 0..9
            const int k0 = kq * 2;
            const int v0 = lane * 2, v2 = lane * 2 + 64;
            u64 a00 = 0, a01 = 0, a10 = 0, a11 = 0;
            const u64* wd = &s->auxd[k0];
            const float* f0p = &s->fs[v0];
            #pragma unroll 2
            for (int c = 0; c < C_IN; ++c) {
                u64 f0 = *reinterpret_cast<const u64*>(f0p + c * TILE);
                u64 f1 = *reinterpret_cast<const u64*>(f0p + c * TILE + 64);
                u64 w0 = wd[c * K_OUT];
                u64 w1v = wd[c * K_OUT + 1];
                fma2(a00, f0, w0); fma2(a01, f0, w1v);
                fma2(a10, f1, w0); fma2(a11, f1, w1v);
            }
            float b0 = s->auxbs[k0], b1v = s->auxbs[k0 + 1];
            float2 p00 = unpk(a00), p01 = unpk(a01);
            float2 p10 = unpk(a10), p11 = unpk(a11);
            int r;
            r = s->ranks[v0];
            if (r >= 0) *reinterpret_cast<float2*>(&outsem[(size_t)r * K_OUT + k0]) = make_float2(p00.x + b0, p01.x + b1v);
            r = s->ranks[v0 + 1];
            if (r >= 0) *reinterpret_cast<float2*>(&outsem[(size_t)r * K_OUT + k0]) = make_float2(p00.y + b0, p01.y + b1v);
            r = s->ranks[v2];
            if (r >= 0) *reinterpret_cast<float2*>(&outsem[(size_t)r * K_OUT + k0]) = make_float2(p10.x + b0, p11.x + b1v);
            r = s->ranks[v2 + 1];
            if (r >= 0) *reinterpret_cast<float2*>(&outsem[(size_t)r * K_OUT + k0]) = make_float2(p10.y + b0, p11.y + b1v);
        }
    }
}

extern "C" void kernel_launch(void* const* d_in, const int* in_sizes, int n_in,
                              void* d_out, int out_size)
{
    const float* x3d   = (const float*)d_in[0];
    const float* w1    = (const float*)d_in[1];
    const float* b1    = (const float*)d_in[2];
    const float* ln_g  = (const float*)d_in[3];
    const float* ln_b  = (const float*)d_in[4];
    const float* w2    = (const float*)d_in[5];
    const float* b2    = (const float*)d_in[6];
    const float* sdb_w = (const float*)d_in[7];
    const float* sdb_b = (const float*)d_in[8];
    const float* ssc_w = (const float*)d_in[9];
    const float* ssc_b = (const float*)d_in[10];
    const float* aux_w = (const float*)d_in[11];
    const float* aux_b = (const float*)d_in[12];
    const int* ui      = (const int*)d_in[13];
    const int* mi      = (const int*)d_in[14];
    float* out         = (float*)d_out;

    int nsm = 0;
    cudaDeviceGetAttribute(&nsm, cudaDevAttrMultiProcessorCount, 0);
    if (nsm <= 0) nsm = 148;

    cudaFuncSetAttribute(fused_kernel,
                         cudaFuncAttributeMaxDynamicSharedMemorySize,
                         (int)sizeof(Smem));

    rank_kernel<<<NVOX / 256, 256>>>(ui, mi);
    fused_kernel<<<nsm, THREADS, sizeof(Smem)>>>(x3d, w1, b1, ln_g, ln_b, w2, b2,
                                                 sdb_w, sdb_b, ssc_w, ssc_b,
                                                 aux_w, aux_b, out);
}

// round 5
// speedup vs baseline: 1.4980x; 1.4980x over previous
#include <cuda_runtime.h>

#define NVOX   262144
#define NU     65536
#define C_IN   128
#define C_HID  64
#define K_OUT  20
#define TILE   128
#define NTILES (NVOX / TILE)
#define HSV    132           // hs row stride (floats), [j][v]
#define THREADS 256

typedef unsigned long long u64;

__device__ __forceinline__ u64 bcast2(float a) {
    u64 r; asm("mov.b64 %0, {%1, %1};" : "=l"(r) : "f"(a)); return r;
}
__device__ __forceinline__ u64 pack2(float a, float b) {
    u64 r; asm("mov.b64 %0, {%1, %2};" : "=l"(r) : "f"(a), "f"(b)); return r;
}
__device__ __forceinline__ void fma2(u64& d, u64 a, u64 b) {
    asm("fma.rn.f32x2 %0, %1, %2, %0;" : "+l"(d) : "l"(a), "l"(b));
}
__device__ __forceinline__ float2 unpk(u64 v) {
    float2 r; asm("mov.b64 {%0, %1}, %2;" : "=f"(r.x), "=f"(r.y) : "l"(v)); return r;
}
__device__ __forceinline__ float leaky(float x) {
    return fmaxf(x, 0.f) + 0.01f * fminf(x, 0.f);
}

__device__ int g_rank[NVOX];

__global__ void rank_kernel(const int* __restrict__ ui, const int* __restrict__ mi) {
    int t = blockIdx.x * blockDim.x + threadIdx.x;
    if (t < NU)        g_rank[ui[t]]      = t;
    else if (t < NVOX) g_rank[mi[t - NU]] = -1;
}

struct __align__(16) Smem {
    float fs[C_IN * TILE];        // [c][v] feats -> vox
    float hs[C_HID * HSV];        // [j][v] hidden, then d
    float w1s [C_IN * C_HID];     // [c][j]
    float sdbs[C_IN * C_HID];     // [c][j]
    float w2s [C_HID * C_IN];     // [j][c]
    float sscs[C_HID * K_OUT];    // [j][k]
    float auxs[C_IN * K_OUT];     // [c][k]
    float b1s[C_HID], lngs[C_HID], lnbs[C_HID], sdbbs[C_HID];
    float b2s[C_IN];
    float sscbs[K_OUT], auxbs[K_OUT];
    float mus[TILE], rss[TILE];
    float red1[2 * TILE], red2[2 * TILE];
    int   ranks[TILE];
    int   lstv[TILE], lstr[TILE];
    int   cnt, pad[3];
};

// GEMM kernel for G1/G3: out64[j][v] (+bias, opt leaky) = in[c][v] @ W[c][j]
// thread: 8 v (4 natural v-pairs) x 4 j; warp = 8 vg x 4 jg.
__device__ __forceinline__ void gemm_128x64(
    Smem* s, const float* __restrict__ fsrc, const float* __restrict__ wsrc,
    const float* __restrict__ bias, bool do_leaky, int t)
{
    const int warp = t >> 5, lane = t & 31;
    const int vg = (warp & 1) * 8 + (lane & 7);       // 0..15
    const int jg = (warp >> 1) * 4 + (lane >> 3);     // 0..15
    const int v0 = vg * 8, j0 = jg * 4;

    u64 acc[4][4];   // [v-pair][j]
    #pragma unroll
    for (int jj = 0; jj < 4; ++jj) {
        u64 b = bcast2(bias[j0 + jj]);
        #pragma unroll
        for (int p = 0; p < 4; ++p) acc[p][jj] = b;
    }
    const float* fp = fsrc + v0;
    const float* wp = wsrc + j0;
    #pragma unroll 4
    for (int c = 0; c < C_IN; ++c) {
        ulonglong2 fa = *reinterpret_cast<const ulonglong2*>(fp + c * TILE);
        ulonglong2 fb = *reinterpret_cast<const ulonglong2*>(fp + c * TILE + 4);
        float4 w = *reinterpret_cast<const float4*>(wp + c * C_HID);
        u64 w0 = bcast2(w.x), w1 = bcast2(w.y), w2d = bcast2(w.z), w3 = bcast2(w.w);
        fma2(acc[0][0], fa.x, w0); fma2(acc[1][0], fa.y, w0); fma2(acc[2][0], fb.x, w0); fma2(acc[3][0], fb.y, w0);
        fma2(acc[0][1], fa.x, w1); fma2(acc[1][1], fa.y, w1); fma2(acc[2][1], fb.x, w1); fma2(acc[3][1], fb.y, w1);
        fma2(acc[0][2], fa.x, w2d); fma2(acc[1][2], fa.y, w2d); fma2(acc[2][2], fb.x, w2d); fma2(acc[3][2], fb.y, w2d);
        fma2(acc[0][3], fa.x, w3); fma2(acc[1][3], fa.y, w3); fma2(acc[2][3], fb.x, w3); fma2(acc[3][3], fb.y, w3);
    }
    #pragma unroll
    for (int jj = 0; jj < 4; ++jj) {
        float* hrow = &s->hs[(j0 + jj) * HSV + v0];
        #pragma unroll
        for (int p = 0; p < 4; ++p) {
            float2 q = unpk(acc[p][jj]);
            if (do_leaky) { q.x = leaky(q.x); q.y = leaky(q.y); }
            *reinterpret_cast<u64*>(hrow + p * 2) = pack2(q.x, q.y);
        }
    }
}

__global__ void __launch_bounds__(THREADS, 1)
fused_kernel(const float* __restrict__ x3d,
             const float* __restrict__ w1,    const float* __restrict__ b1,
             const float* __restrict__ ln_g,  const float* __restrict__ ln_b,
             const float* __restrict__ w2,    const float* __restrict__ b2,
             const float* __restrict__ sdb_w, const float* __restrict__ sdb_b,
             const float* __restrict__ ssc_w, const float* __restrict__ ssc_b,
             const float* __restrict__ aux_w, const float* __restrict__ aux_b,
             float* __restrict__ out)
{
    extern __shared__ char smem_raw[];
    Smem* s = reinterpret_cast<Smem*>(smem_raw);
    const int t = threadIdx.x;
    const int warp = t >> 5, lane = t & 31;

    for (int i = t; i < C_IN * C_HID;  i += THREADS) s->w1s[i]  = w1[i];
    for (int i = t; i < C_HID * C_IN;  i += THREADS) s->w2s[i]  = w2[i];
    for (int i = t; i < C_IN * C_HID;  i += THREADS) s->sdbs[i] = sdb_w[i];
    for (int i = t; i < C_HID * K_OUT; i += THREADS) s->sscs[i] = ssc_w[i];
    for (int i = t; i < C_IN * K_OUT;  i += THREADS) s->auxs[i] = aux_w[i];
    if (t < C_HID) { s->b1s[t] = b1[t]; s->lngs[t] = ln_g[t]; s->lnbs[t] = ln_b[t]; s->sdbbs[t] = sdb_b[t]; }
    if (t < C_IN)  { s->b2s[t] = b2[t]; }
    if (t < K_OUT) { s->sscbs[t] = ssc_b[t]; s->auxbs[t] = aux_b[t]; }

    float* outsem = out + (size_t)K_OUT * NVOX;

    for (int tile = blockIdx.x; tile < NTILES; tile += gridDim.x) {
        const int vbase = tile * TILE;
        __syncthreads();                       // previous tile fully consumed
        if (t == 0) s->cnt = 0;

        // ---- load feats tile [128 c][128 v] ----
        #pragma unroll
        for (int it = 0; it < 16; ++it) {
            int i  = t + it * THREADS;         // 0..4095 float4s
            int c  = i >> 5;
            int vq = i & 31;
            *reinterpret_cast<float4*>(&s->fs[c * TILE + vq * 4]) =
                *reinterpret_cast<const float4*>(&x3d[(size_t)c * NVOX + vbase + vq * 4]);
        }
        if (t < TILE) s->ranks[t] = g_rank[vbase + t];
        __syncthreads();
        if (t < TILE) {
            int r = s->ranks[t];
            if (r >= 0) { int p = atomicAdd(&s->cnt, 1); s->lstv[p] = t; s->lstr[p] = r; }
        }

        // ---- GEMM1: h = feats @ w1 + b1 ----
        gemm_128x64(s, s->fs, s->w1s, s->b1s, false, t);
        __syncthreads();

        // ---- LayerNorm stats (2 threads per voxel) ----
        {
            int v = t & 127, half = t >> 7;
            float sum = 0.f, ssum = 0.f;
            #pragma unroll 8
            for (int jj = 0; jj < 32; ++jj) {
                float x = s->hs[(half * 32 + jj) * HSV + v];
                sum += x; ssum += x * x;
            }
            s->red1[half * TILE + v] = sum;
            s->red2[half * TILE + v] = ssum;
        }
        __syncthreads();
        if (t < TILE) {
            float sum  = s->red1[t] + s->red1[TILE + t];
            float ssum = s->red2[t] + s->red2[TILE + t];
            float mu  = sum * (1.f / 64.f);
            float var = ssum * (1.f / 64.f) - mu * mu;
            s->mus[t] = mu;
            s->rss[t] = rsqrtf(var + 1e-5f);
        }
        __syncthreads();
        #pragma unroll
        for (int it = 0; it < 32; ++it) {
            int i = t + it * THREADS;          // 0..8191
            int j = i >> 7, v = i & 127;
            float x = s->hs[j * HSV + v];
            x = (x - s->mus[v]) * s->rss[v] * s->lngs[j] + s->lnbs[j];
            s->hs[j * HSV + v] = leaky(x);
        }
        __syncthreads();

        // ---- GEMM2: prior = h @ w2 + b2 ; warp owns 16-c block, lane owns v-quad ----
        {
            const int c0 = warp * 16;
            const int v0 = lane * 4;
            u64 acc[4][8];                     // [vv][c-pair]
            #pragma unroll
            for (int cp = 0; cp < 8; ++cp) {
                u64 b = *reinterpret_cast<const u64*>(&s->b2s[c0 + cp * 2]);
                #pragma unroll
                for (int vv = 0; vv < 4; ++vv) acc[vv][cp] = b;
            }
            const float* hp = &s->hs[v0];
            const float* wp = &s->w2s[c0];
            #pragma unroll 2
            for (int j = 0; j < C_HID; ++j) {
                float4 f = *reinterpret_cast<const float4*>(hp + j * HSV);
                u64 d0 = bcast2(f.x), d1 = bcast2(f.y), d2 = bcast2(f.z), d3 = bcast2(f.w);
                ulonglong2 wa = *reinterpret_cast<const ulonglong2*>(wp + j * C_IN);
                ulonglong2 wb = *reinterpret_cast<const ulonglong2*>(wp + j * C_IN + 4);
                ulonglong2 wc = *reinterpret_cast<const ulonglong2*>(wp + j * C_IN + 8);
                ulonglong2 wd = *reinterpret_cast<const ulonglong2*>(wp + j * C_IN + 12);
                fma2(acc[0][0], d0, wa.x); fma2(acc[1][0], d1, wa.x); fma2(acc[2][0], d2, wa.x); fma2(acc[3][0], d3, wa.x);
                fma2(acc[0][1], d0, wa.y); fma2(acc[1][1], d1, wa.y); fma2(acc[2][1], d2, wa.y); fma2(acc[3][1], d3, wa.y);
                fma2(acc[0][2], d0, wb.x); fma2(acc[1][2], d1, wb.x); fma2(acc[2][2], d2, wb.x); fma2(acc[3][2], d3, wb.x);
                fma2(acc[0][3], d0, wb.y); fma2(acc[1][3], d1, wb.y); fma2(acc[2][3], d2, wb.y); fma2(acc[3][3], d3, wb.y);
                fma2(acc[0][4], d0, wc.x); fma2(acc[1][4], d1, wc.x); fma2(acc[2][4], d2, wc.x); fma2(acc[3][4], d3, wc.x);
                fma2(acc[0][5], d0, wc.y); fma2(acc[1][5], d1, wc.y); fma2(acc[2][5], d2, wc.y); fma2(acc[3][5], d3, wc.y);
                fma2(acc[0][6], d0, wd.x); fma2(acc[1][6], d1, wd.x); fma2(acc[2][6], d2, wd.x); fma2(acc[3][6], d3, wd.x);
                fma2(acc[0][7], d0, wd.y); fma2(acc[1][7], d1, wd.y); fma2(acc[2][7], d2, wd.y); fma2(acc[3][7], d3, wd.y);
            }
            // merge masked voxels into fs (conflict-free: contiguous v within warp, one c row per store)
            #pragma unroll
            for (int vv = 0; vv < 4; ++vv) {
                if (s->ranks[v0 + vv] < 0) {
                    #pragma unroll
                    for (int cp = 0; cp < 8; ++cp) {
                        float2 q = unpk(acc[vv][cp]);
                        s->fs[(c0 + cp * 2)     * TILE + v0 + vv] = q.x;
                        s->fs[(c0 + cp * 2 + 1) * TILE + v0 + vv] = q.y;
                    }
                }
            }
        }
        __syncthreads();

        // ---- GEMM3: d = leaky(vox @ sdb_w + sdb_b) -> hs ----
        gemm_128x64(s, s->fs, s->sdbs, s->sdbbs, true, t);
        __syncthreads();

        // ---- heads: warps 0-4 SSC, warps 5-7 AUX ----
        if (warp < 5) {
            const int k0 = warp * 4;
            const int v0 = lane * 4;
            u64 acc[2][4];                     // [v-pair][k]
            #pragma unroll
            for (int kk = 0; kk < 4; ++kk) {
                u64 b = bcast2(s->sscbs[k0 + kk]);
                acc[0][kk] = b; acc[1][kk] = b;
            }
            const float* hp = &s->hs[v0];
            const float* wp = &s->sscs[k0];
            #pragma unroll 4
            for (int j = 0; j < C_HID; ++j) {
                ulonglong2 f = *reinterpret_cast<const ulonglong2*>(hp + j * HSV);
                float4 w = *reinterpret_cast<const float4*>(wp + j * K_OUT);
                u64 w0 = bcast2(w.x), w1v = bcast2(w.y), w2v = bcast2(w.z), w3 = bcast2(w.w);
                fma2(acc[0][0], f.x, w0);  fma2(acc[1][0], f.y, w0);
                fma2(acc[0][1], f.x, w1v); fma2(acc[1][1], f.y, w1v);
                fma2(acc[0][2], f.x, w2v); fma2(acc[1][2], f.y, w2v);
                fma2(acc[0][3], f.x, w3);  fma2(acc[1][3], f.y, w3);
            }
            #pragma unroll
            for (int kk = 0; kk < 4; ++kk) {
                float* op = &out[(size_t)(k0 + kk) * NVOX + vbase + v0];
                *reinterpret_cast<u64*>(op)     = acc[0][kk];
                *reinterpret_cast<u64*>(op + 2) = acc[1][kk];
            }
        } else {
            const int nu = s->cnt;
            for (int i = lane + (warp - 5) * 32; i < nu; i += 96) {
                int v = s->lstv[i], r = s->lstr[i];
                u64 acc[10];
                const u64* bb = reinterpret_cast<const u64*>(s->auxbs);
                #pragma unroll
                for (int kp = 0; kp < 10; ++kp) acc[kp] = bb[kp];
                const float* fcol = &s->fs[v];
                #pragma unroll 4
                for (int c = 0; c < C_IN; ++c) {
                    u64 fb = bcast2(fcol[c * TILE]);
                    const u64* wr = reinterpret_cast<const u64*>(&s->auxs[c * K_OUT]);
                    #pragma unroll
                    for (int kp = 0; kp < 10; ++kp) fma2(acc[kp], fb, wr[kp]);
                }
                u64* orow = reinterpret_cast<u64*>(&outsem[(size_t)r * K_OUT]);
                #pragma unroll
                for (int kp = 0; kp < 10; ++kp) orow[kp] = acc[kp];
            }
        }
    }
}

extern "C" void kernel_launch(void* const* d_in, const int* in_sizes, int n_in,
                              void* d_out, int out_size)
{
    const float* x3d   = (const float*)d_in[0];
    const float* w1    = (const float*)d_in[1];
    const float* b1    = (const float*)d_in[2];
    const float* ln_g  = (const float*)d_in[3];
    const float* ln_b  = (const float*)d_in[4];
    const float* w2    = (const float*)d_in[5];
    const float* b2    = (const float*)d_in[6];
    const float* sdb_w = (const float*)d_in[7];
    const float* sdb_b = (const float*)d_in[8];
    const float* ssc_w = (const float*)d_in[9];
    const float* ssc_b = (const float*)d_in[10];
    const float* aux_w = (const float*)d_in[11];
    const float* aux_b = (const float*)d_in[12];
    const int* ui      = (const int*)d_in[13];
    const int* mi      = (const int*)d_in[14];
    float* out         = (float*)d_out;

    int nsm = 0;
    cudaDeviceGetAttribute(&nsm, cudaDevAttrMultiProcessorCount, 0);
    if (nsm <= 0) nsm = 148;

    cudaFuncSetAttribute(fused_kernel,
                         cudaFuncAttributeMaxDynamicSharedMemorySize,
                         (int)sizeof(Smem));

    rank_kernel<<<NVOX / 256, 256>>>(ui, mi);
    fused_kernel<<<nsm, THREADS, sizeof(Smem)>>>(x3d, w1, b1, ln_g, ln_b, w2, b2,
                                                 sdb_w, sdb_b, ssc_w, ssc_b,
                                                 aux_w, aux_b, out);
}

// round 6
// speedup vs baseline: 1.7751x; 1.1850x over previous
#include <cuda_runtime.h>

#define NVOX   262144
#define NU     65536
#define C_IN   128
#define C_HID  64
#define K_OUT  20
#define TILE   128
#define NTILES (NVOX / TILE)
#define HSV    132           // hs row stride, [j][v]
#define THREADS 512

typedef unsigned long long u64;

__device__ __forceinline__ u64 bcast2(float a) {
    u64 r; asm("mov.b64 %0, {%1, %1};" : "=l"(r) : "f"(a)); return r;
}
__device__ __forceinline__ void fma2(u64& d, u64 a, u64 b) {
    asm("fma.rn.f32x2 %0, %1, %2, %0;" : "+l"(d) : "l"(a), "l"(b));
}
__device__ __forceinline__ float2 unpk(u64 v) {
    float2 r; asm("mov.b64 {%0, %1}, %2;" : "=f"(r.x), "=f"(r.y) : "l"(v)); return r;
}
__device__ __forceinline__ float leaky(float x) {
    return fmaxf(x, 0.f) + 0.01f * fminf(x, 0.f);
}

__device__ int g_rank[NVOX];

__global__ void rank_kernel(const int* __restrict__ ui, const int* __restrict__ mi) {
    int t = blockIdx.x * blockDim.x + threadIdx.x;
    if (t < NU)        g_rank[ui[t]]      = t;
    else if (t < NVOX) g_rank[mi[t - NU]] = -1;
}

struct __align__(16) Smem {
    float fs[C_IN * TILE];        // [c][v] feats -> vox
    float hs[C_HID * HSV];        // [j][v] hidden, then d
    float w1s [C_IN * C_HID];     // [c][j]
    float sdbs[C_IN * C_HID];     // [c][j]
    float w2s [C_HID * C_IN];     // [j][c]
    float sscs[C_HID * K_OUT];    // [j][k]
    float auxs[C_IN * K_OUT];     // [c][k]
    float b1s[C_HID], lngs[C_HID], lnbs[C_HID], sdbbs[C_HID];
    float b2s[C_IN];
    float sscbs[K_OUT], auxbs[K_OUT];
    float mus[TILE], rss[TILE];
    float red1[4 * TILE], red2[4 * TILE];
    int   ranks[TILE];
    int   lstv[TILE], lstr[TILE];
    int   cnt, pad[3];
};

// G1/G3: hs[j][v] = (opt leaky)(in[c][v] @ W[c][j] + bias), 128v x 64j, K=128.
// 16 warps; warp = 16 v-pairs x 2 j-blocks; thread = 2v x 8j (acc[2v][4 j-pairs]).
__device__ __forceinline__ void gemm_128x64(
    Smem* s, const float* __restrict__ fsrc, const float* __restrict__ wsrc,
    const float* __restrict__ bias, bool do_leaky, int t)
{
    const int warp = t >> 5, lane = t & 31;
    const int vp   = (warp & 3) * 16 + (lane & 15);   // v-pair 0..63
    const int jblk = (warp >> 2) * 2 + (lane >> 4);   // 0..7
    const int v0 = vp * 2, j0 = jblk * 8;

    u64 acc[2][4];
    {
        const u64* bp = reinterpret_cast<const u64*>(bias + j0);
        #pragma unroll
        for (int jp = 0; jp < 4; ++jp) { acc[0][jp] = bp[jp]; acc[1][jp] = bp[jp]; }
    }
    const float* fp = fsrc + v0;
    const float* wp = wsrc + j0;
    #pragma unroll 4
    for (int c = 0; c < C_IN; ++c) {
        float2 f = *reinterpret_cast<const float2*>(fp + c * TILE);
        u64 d0 = bcast2(f.x), d1 = bcast2(f.y);
        ulonglong2 wa = *reinterpret_cast<const ulonglong2*>(wp + c * C_HID);
        ulonglong2 wb = *reinterpret_cast<const ulonglong2*>(wp + c * C_HID + 4);
        fma2(acc[0][0], d0, wa.x); fma2(acc[1][0], d1, wa.x);
        fma2(acc[0][1], d0, wa.y); fma2(acc[1][1], d1, wa.y);
        fma2(acc[0][2], d0, wb.x); fma2(acc[1][2], d1, wb.x);
        fma2(acc[0][3], d0, wb.y); fma2(acc[1][3], d1, wb.y);
    }
    #pragma unroll
    for (int jp = 0; jp < 4; ++jp) {
        #pragma unroll
        for (int vv = 0; vv < 2; ++vv) {
            float2 q = unpk(acc[vv][jp]);
            if (do_leaky) { q.x = leaky(q.x); q.y = leaky(q.y); }
            s->hs[(j0 + 2 * jp)     * HSV + v0 + vv] = q.x;
            s->hs[(j0 + 2 * jp + 1) * HSV + v0 + vv] = q.y;
        }
    }
}

__global__ void __launch_bounds__(THREADS, 1)
fused_kernel(const float* __restrict__ x3d,
             const float* __restrict__ w1,    const float* __restrict__ b1,
             const float* __restrict__ ln_g,  const float* __restrict__ ln_b,
             const float* __restrict__ w2,    const float* __restrict__ b2,
             const float* __restrict__ sdb_w, const float* __restrict__ sdb_b,
             const float* __restrict__ ssc_w, const float* __restrict__ ssc_b,
             const float* __restrict__ aux_w, const float* __restrict__ aux_b,
             float* __restrict__ out)
{
    extern __shared__ char smem_raw[];
    Smem* s = reinterpret_cast<Smem*>(smem_raw);
    const int t = threadIdx.x;
    const int warp = t >> 5, lane = t & 31;

    for (int i = t; i < C_IN * C_HID;  i += THREADS) s->w1s[i]  = w1[i];
    for (int i = t; i < C_HID * C_IN;  i += THREADS) s->w2s[i]  = w2[i];
    for (int i = t; i < C_IN * C_HID;  i += THREADS) s->sdbs[i] = sdb_w[i];
    for (int i = t; i < C_HID * K_OUT; i += THREADS) s->sscs[i] = ssc_w[i];
    for (int i = t; i < C_IN * K_OUT;  i += THREADS) s->auxs[i] = aux_w[i];
    if (t < C_HID) { s->b1s[t] = b1[t]; s->lngs[t] = ln_g[t]; s->lnbs[t] = ln_b[t]; s->sdbbs[t] = sdb_b[t]; }
    if (t < C_IN)  { s->b2s[t] = b2[t]; }
    if (t < K_OUT) { s->sscbs[t] = ssc_b[t]; s->auxbs[t] = aux_b[t]; }

    float* outsem = out + (size_t)K_OUT * NVOX;

    for (int tile = blockIdx.x; tile < NTILES; tile += gridDim.x) {
        const int vbase = tile * TILE;
        __syncthreads();
        if (t == 0) s->cnt = 0;

        // ---- load feats tile [128 c][128 v] ----
        #pragma unroll
        for (int it = 0; it < 8; ++it) {
            int i  = t + it * THREADS;
            int c  = i >> 5;
            int vq = i & 31;
            *reinterpret_cast<float4*>(&s->fs[c * TILE + vq * 4]) =
                *reinterpret_cast<const float4*>(&x3d[(size_t)c * NVOX + vbase + vq * 4]);
        }
        if (t < TILE) s->ranks[t] = g_rank[vbase + t];
        __syncthreads();
        if (t < TILE) {
            int r = s->ranks[t];
            if (r >= 0) { int p = atomicAdd(&s->cnt, 1); s->lstv[p] = t; s->lstr[p] = r; }
        }

        // ---- GEMM1 ----
        gemm_128x64(s, s->fs, s->w1s, s->b1s, false, t);
        __syncthreads();

        // ---- LayerNorm stats (4 threads per voxel) ----
        {
            int v = t & 127, q = t >> 7;
            float sum = 0.f, ssum = 0.f;
            #pragma unroll 8
            for (int jj = 0; jj < 16; ++jj) {
                float x = s->hs[(q * 16 + jj) * HSV + v];
                sum += x; ssum += x * x;
            }
            s->red1[q * TILE + v] = sum;
            s->red2[q * TILE + v] = ssum;
        }
        __syncthreads();
        if (t < TILE) {
            float sum  = s->red1[t] + s->red1[TILE + t] + s->red1[2*TILE + t] + s->red1[3*TILE + t];
            float ssum = s->red2[t] + s->red2[TILE + t] + s->red2[2*TILE + t] + s->red2[3*TILE + t];
            float mu  = sum * (1.f / 64.f);
            float var = ssum * (1.f / 64.f) - mu * mu;
            s->mus[t] = mu;
            s->rss[t] = rsqrtf(var + 1e-5f);
        }
        __syncthreads();
        #pragma unroll
        for (int it = 0; it < 16; ++it) {
            int i = t + it * THREADS;
            int j = i >> 7, v = i & 127;
            float x = s->hs[j * HSV + v];
            x = (x - s->mus[v]) * s->rss[v] * s->lngs[j] + s->lnbs[j];
            s->hs[j * HSV + v] = leaky(x);
        }
        __syncthreads();

        // ---- GEMM2: prior = h @ w2 + b2 ; warp owns 8 c, lane owns 4 strided v ----
        {
            const int c0 = warp * 8;
            bool m[4];
            #pragma unroll
            for (int q = 0; q < 4; ++q) m[q] = s->ranks[lane + 32 * q] < 0;
            u64 acc[4][4];
            {
                const u64* bp = reinterpret_cast<const u64*>(&s->b2s[c0]);
                #pragma unroll
                for (int cp = 0; cp < 4; ++cp) {
                    u64 b = bp[cp];
                    #pragma unroll
                    for (int q = 0; q < 4; ++q) acc[q][cp] = b;
                }
            }
            const float* hp = &s->hs[lane];
            const float* wp = &s->w2s[c0];
            #pragma unroll 2
            for (int j = 0; j < C_HID; ++j) {
                u64 d0 = bcast2(hp[j * HSV]);
                u64 d1 = bcast2(hp[j * HSV + 32]);
                u64 d2 = bcast2(hp[j * HSV + 64]);
                u64 d3 = bcast2(hp[j * HSV + 96]);
                ulonglong2 wa = *reinterpret_cast<const ulonglong2*>(wp + j * C_IN);
                ulonglong2 wb = *reinterpret_cast<const ulonglong2*>(wp + j * C_IN + 4);
                fma2(acc[0][0], d0, wa.x); fma2(acc[1][0], d1, wa.x); fma2(acc[2][0], d2, wa.x); fma2(acc[3][0], d3, wa.x);
                fma2(acc[0][1], d0, wa.y); fma2(acc[1][1], d1, wa.y); fma2(acc[2][1], d2, wa.y); fma2(acc[3][1], d3, wa.y);
                fma2(acc[0][2], d0, wb.x); fma2(acc[1][2], d1, wb.x); fma2(acc[2][2], d2, wb.x); fma2(acc[3][2], d3, wb.x);
                fma2(acc[0][3], d0, wb.y); fma2(acc[1][3], d1, wb.y); fma2(acc[2][3], d2, wb.y); fma2(acc[3][3], d3, wb.y);
            }
            // merge masked voxels into fs: warp writes one c row at a time, contiguous v
            #pragma unroll
            for (int cp = 0; cp < 4; ++cp) {
                float* r0 = &s->fs[(c0 + 2 * cp)     * TILE];
                float* r1 = &s->fs[(c0 + 2 * cp + 1) * TILE];
                #pragma unroll
                for (int q = 0; q < 4; ++q) {
                    float2 pr = unpk(acc[q][cp]);
                    if (m[q]) { r0[lane + 32 * q] = pr.x; r1[lane + 32 * q] = pr.y; }
                }
            }
        }
        __syncthreads();

        // ---- GEMM3 ----
        gemm_128x64(s, s->fs, s->sdbs, s->sdbbs, true, t);
        __syncthreads();

        // ---- heads: warps 0-9 SSC (k-pair each), warps 10-15 AUX ----
        if (warp < 10) {
            const int k0 = warp * 2;
            u64 acc[4];
            {
                u64 b; { float2 bb = make_float2(s->sscbs[k0], s->sscbs[k0 + 1]);
                         asm("mov.b64 %0, {%1, %2};" : "=l"(b) : "f"(bb.x), "f"(bb.y)); }
                #pragma unroll
                for (int q = 0; q < 4; ++q) acc[q] = b;
            }
            const float* hp = &s->hs[lane];
            const float* wp = &s->sscs[k0];
            #pragma unroll 4
            for (int j = 0; j < C_HID; ++j) {
                u64 wpair = *reinterpret_cast<const u64*>(wp + j * K_OUT);
                fma2(acc[0], bcast2(hp[j * HSV]),      wpair);
                fma2(acc[1], bcast2(hp[j * HSV + 32]), wpair);
                fma2(acc[2], bcast2(hp[j * HSV + 64]), wpair);
                fma2(acc[3], bcast2(hp[j * HSV + 96]), wpair);
            }
            float* o0 = &out[(size_t)k0 * NVOX + vbase];
            float* o1 = &out[(size_t)(k0 + 1) * NVOX + vbase];
            #pragma unroll
            for (int q = 0; q < 4; ++q) {
                float2 pr = unpk(acc[q]);
                o0[lane + 32 * q] = pr.x;
                o1[lane + 32 * q] = pr.y;
            }
        } else {
            const int nu = s->cnt;
            for (int i = lane + (warp - 10) * 32; i < nu; i += 192) {
                int v = s->lstv[i], r = s->lstr[i];
                u64 acc[10];
                const u64* bb = reinterpret_cast<const u64*>(s->auxbs);
                #pragma unroll
                for (int kp = 0; kp < 10; ++kp) acc[kp] = bb[kp];
                const float* fcol = &s->fs[v];
                #pragma unroll 4
                for (int c = 0; c < C_IN; ++c) {
                    u64 fb = bcast2(fcol[c * TILE]);
                    const u64* wr = reinterpret_cast<const u64*>(&s->auxs[c * K_OUT]);
                    #pragma unroll
                    for (int kp = 0; kp < 10; ++kp) fma2(acc[kp], fb, wr[kp]);
                }
                u64* orow = reinterpret_cast<u64*>(&outsem[(size_t)r * K_OUT]);
                #pragma unroll
                for (int kp = 0; kp < 10; ++kp) orow[kp] = acc[kp];
            }
        }
    }
}

extern "C" void kernel_launch(void* const* d_in, const int* in_sizes, int n_in,
                              void* d_out, int out_size)
{
    const float* x3d   = (const float*)d_in[0];
    const float* w1    = (const float*)d_in[1];
    const float* b1    = (const float*)d_in[2];
    const float* ln_g  = (const float*)d_in[3];
    const float* ln_b  = (const float*)d_in[4];
    const float* w2    = (const float*)d_in[5];
    const float* b2    = (const float*)d_in[6];
    const float* sdb_w = (const float*)d_in[7];
    const float* sdb_b = (const float*)d_in[8];
    const float* ssc_w = (const float*)d_in[9];
    const float* ssc_b = (const float*)d_in[10];
    const float* aux_w = (const float*)d_in[11];
    const float* aux_b = (const float*)d_in[12];
    const int* ui      = (const int*)d_in[13];
    const int* mi      = (const int*)d_in[14];
    float* out         = (float*)d_out;

    int nsm = 0;
    cudaDeviceGetAttribute(&nsm, cudaDevAttrMultiProcessorCount, 0);
    if (nsm <= 0) nsm = 148;

    cudaFuncSetAttribute(fused_kernel,
                         cudaFuncAttributeMaxDynamicSharedMemorySize,
                         (int)sizeof(Smem));

    rank_kernel<<<NVOX / 256, 256>>>(ui, mi);
    fused_kernel<<<nsm, THREADS, sizeof(Smem)>>>(x3d, w1, b1, ln_g, ln_b, w2, b2,
                                                 sdb_w, sdb_b, ssc_w, ssc_b,
                                                 aux_w, aux_b, out);
}